// round 4
// baseline (speedup 1.0000x reference)
#include <cuda_runtime.h>

#define NV    8192
#define NCAM  20
#define CIN   2048
#define NH    4
#define NCOUT 2048
#define NJ    8192      /* NH*NCOUT */
#define NE    16384
#define NEG_SLOPE 0.2f
#define KB    16        /* k-split chunks for h_src */
#define KC    128       /* K per chunk (KB*KC = CIN) */

// ---------------- scratch (device globals; no allocation) ----------------
__device__ float    g_part[KB * NCAM * NJ];   // 10.5MB k-split partials
__device__ float    g_hsrc[NCAM * NJ];        // [cam][h*COUT + c]
__device__ float    g_wd[NH * CIN];           // [h][k]
__device__ float    g_as[NCAM * NH];
__device__ float    g_ad[NV * NH];
__device__ int      g_cnt[NV * NCAM];         // per-vehicle camera edge counts
__device__ unsigned g_cmask[NV];              // active-camera bitmask
__device__ float    g_coef[NV * NCAM * NH];   // cnt * softmax weight
__device__ int      g_is64;

// ---------------- helpers ----------------
__device__ __forceinline__ float warp_sum(float v) {
    #pragma unroll
    for (int o = 16; o; o >>= 1) v += __shfl_down_sync(0xffffffffu, v, o);
    return v;
}
__device__ __forceinline__ int eidx(const void* p, int i) {
    return g_is64 ? (int)((const long long*)p)[i] : ((const int*)p)[i];
}

// ---------------- 1) zero accumulated scratch + int-width detect ----------------
__global__ void k_zero(const void* esrc) {
    int i = blockIdx.x * blockDim.x + threadIdx.x;
    if (i == 0) {
        const long long* p = (const long long*)esrc;
        int ok = 1;
        for (int q = 0; q < 64; q++) {
            long long v = p[q];
            if (v < 0 || v >= NCAM) { ok = 0; break; }
        }
        g_is64 = ok;
    }
    int s = gridDim.x * blockDim.x;
    for (int j = i; j < NV * NCAM; j += s) g_cnt[j] = 0;
    for (int j = i; j < NH * CIN; j += s)  g_wd[j] = 0.f;
    for (int j = i; j < NCAM * NH; j += s) g_as[j] = 0.f;
}

// ---------------- 2) fused: h_src partials + wd, single W pass ----------------
// grid (32 j-blocks of 256 cols, 16 k-chunks of 128); 128 threads; 2 cols/thread.
__global__ void __launch_bounds__(128) k_hsrc(const float* __restrict__ W,
                                              const float* __restrict__ cam,
                                              const float* __restrict__ att_dst) {
    int jb = blockIdx.x, kb = blockIdx.y, t = threadIdx.x;
    int wid = t >> 5, lane = t & 31;
    int k0 = kb * KC;
    int j0 = jb * 256 + t * 2;
    int h  = jb >> 3;                       // 256 cols/block, 2048 per head

    __shared__ float  s_cam[NCAM][KC];      // 10KB
    __shared__ float  s_wdw[KC][4];         // per-(k, warp) wd partials

    for (int i = t; i < NCAM * KC; i += 128) {
        int n = i / KC, kc = i % KC;
        s_cam[n][kc] = cam[n * CIN + k0 + kc];
    }
    float2 ad = *(const float2*)(att_dst + j0);
    __syncthreads();

    float acc[NCAM][2];
    #pragma unroll
    for (int n = 0; n < NCAM; n++) { acc[n][0] = 0.f; acc[n][1] = 0.f; }

    const float* Wp = W + (size_t)k0 * NJ + j0;
    #pragma unroll 4
    for (int kc = 0; kc < KC; kc++) {
        float2 w = *(const float2*)(Wp + (size_t)kc * NJ);
        float wdp = warp_sum(w.x * ad.x + w.y * ad.y);
        if (lane == 0) s_wdw[kc][wid] = wdp;
        #pragma unroll
        for (int n = 0; n < NCAM; n++) {
            float c = s_cam[n][kc];
            acc[n][0] += c * w.x;
            acc[n][1] += c * w.y;
        }
    }

    float* pp = g_part + (size_t)kb * (NCAM * NJ) + j0;
    #pragma unroll
    for (int n = 0; n < NCAM; n++)
        *(float2*)(pp + n * NJ) = make_float2(acc[n][0], acc[n][1]);

    __syncthreads();
    // 128 threads cover KC=128 k values
    {
        float s = s_wdw[t][0] + s_wdw[t][1] + s_wdw[t][2] + s_wdw[t][3];
        atomicAdd(&g_wd[h * CIN + k0 + t], s);   // 8 jb-blocks per head per addr
    }
}

// ---------------- 3) reduce partials -> h_src (float4), fused a_s ----------------
__global__ void __launch_bounds__(256) k_hred(const float* __restrict__ att_src) {
    int gid = blockIdx.x * 256 + threadIdx.x;     // over NCAM*NJ/4 = 40960
    int lane = threadIdx.x & 31;
    int j4 = (gid % (NJ / 4));
    int cm = gid / (NJ / 4);
    int j = j4 * 4, h = j / NCOUT;
    float4 s = make_float4(0.f, 0.f, 0.f, 0.f);
    const float4* P = (const float4*)g_part;
    #pragma unroll
    for (int kb = 0; kb < KB; kb++) {
        float4 v = P[(size_t)kb * (NCAM * NJ / 4) + gid];
        s.x += v.x; s.y += v.y; s.z += v.z; s.w += v.w;
    }
    ((float4*)g_hsrc)[gid] = s;
    float4 a = *(const float4*)(att_src + j);
    float p = warp_sum(s.x * a.x + s.y * a.y + s.z * a.z + s.w * a.w);
    if (lane == 0) atomicAdd(&g_as[cm * NH + h], p);
}

// ---------------- 4) a_d: 2 vehicles per warp, 16 per block ----------------
__global__ void __launch_bounds__(256) k_ad(const float* __restrict__ x) {
    __shared__ __align__(16) float s_wd[NH * CIN];   // 32KB
    int t = threadIdx.x, wid = t >> 5, lane = t & 31;
    for (int i = t; i < NH * CIN; i += 256) s_wd[i] = g_wd[i];
    __syncthreads();

    int v0 = blockIdx.x * 16 + wid * 2;
    const float4* xr0 = (const float4*)(x + (size_t)v0 * CIN);
    const float4* xr1 = (const float4*)(x + (size_t)(v0 + 1) * CIN);
    const float4* wd4 = (const float4*)s_wd;
    float p0[NH] = {0.f, 0.f, 0.f, 0.f};
    float p1[NH] = {0.f, 0.f, 0.f, 0.f};
    #pragma unroll 4
    for (int i = 0; i < 16; i++) {
        int idx = lane + i * 32;
        float4 a = xr0[idx];
        float4 b = xr1[idx];
        #pragma unroll
        for (int h = 0; h < NH; h++) {
            float4 wq = wd4[h * (CIN / 4) + idx];
            p0[h] += a.x * wq.x + a.y * wq.y + a.z * wq.z + a.w * wq.w;
            p1[h] += b.x * wq.x + b.y * wq.y + b.z * wq.z + b.w * wq.w;
        }
    }
    #pragma unroll
    for (int h = 0; h < NH; h++) {
        float s0 = warp_sum(p0[h]);
        float s1 = warp_sum(p1[h]);
        if (lane == 0) { g_ad[v0 * NH + h] = s0; g_ad[(v0 + 1) * NH + h] = s1; }
    }
}

// ---------------- 5) edge counts ----------------
__global__ void k_count(const void* esrc, const void* edst) {
    int e = blockIdx.x * blockDim.x + threadIdx.x;
    if (e >= NE) return;
    int s = eidx(esrc, e), d = eidx(edst, e);
    atomicAdd(&g_cnt[d * NCAM + s], 1);
}

// ---------------- 6) per-vehicle softmax over active cameras ----------------
__global__ void k_attn() {
    int v = blockIdx.x * blockDim.x + threadIdx.x;
    if (v >= NV) return;
    unsigned mask = 0;
    int cnt[NCAM];
    const int4* cp = (const int4*)&g_cnt[v * NCAM];
    #pragma unroll
    for (int q = 0; q < 5; q++) {
        int4 c4 = cp[q];
        cnt[q * 4 + 0] = c4.x; cnt[q * 4 + 1] = c4.y;
        cnt[q * 4 + 2] = c4.z; cnt[q * 4 + 3] = c4.w;
    }
    #pragma unroll
    for (int s = 0; s < NCAM; s++) if (cnt[s]) mask |= 1u << s;
    g_cmask[v] = mask;
    if (!mask) return;
    float4 adv = *(const float4*)&g_ad[v * NH];
    float ad[NH] = {adv.x, adv.y, adv.z, adv.w};
    float m[NH] = {-1e30f, -1e30f, -1e30f, -1e30f};
    unsigned mm = mask;
    while (mm) {
        int s = __ffs(mm) - 1; mm &= mm - 1;
        #pragma unroll
        for (int h = 0; h < NH; h++) {
            float z = g_as[s * NH + h] + ad[h];
            z = (z > 0.f) ? z : NEG_SLOPE * z;
            m[h] = fmaxf(m[h], z);
        }
    }
    float den[NH] = {0.f, 0.f, 0.f, 0.f};
    mm = mask;
    while (mm) {
        int s = __ffs(mm) - 1; mm &= mm - 1;
        float p[NH];
        #pragma unroll
        for (int h = 0; h < NH; h++) {
            float z = g_as[s * NH + h] + ad[h];
            z = (z > 0.f) ? z : NEG_SLOPE * z;
            p[h] = (float)cnt[s] * expf(z - m[h]);
            den[h] += p[h];
        }
        *(float4*)&g_coef[(v * NCAM + s) * NH] = make_float4(p[0], p[1], p[2], p[3]);
    }
    float4 r = make_float4(1.f / den[0], 1.f / den[1], 1.f / den[2], 1.f / den[3]);
    mm = mask;
    while (mm) {
        int s = __ffs(mm) - 1; mm &= mm - 1;
        float4 pv = *(const float4*)&g_coef[(v * NCAM + s) * NH];
        pv.x *= r.x; pv.y *= r.y; pv.z *= r.z; pv.w *= r.w;
        *(float4*)&g_coef[(v * NCAM + s) * NH] = pv;
    }
}

// ---------------- 7) fused epilogue (float4) ----------------
// out = x + a*bias + (a/4) * sum_{active cams} coef[v,cam,h] * h_src[cam,h,:]
// grid.x = CIN/1024 = 2 (each block: 256 thr * 4 cols = 1024 cols)
__global__ void __launch_bounds__(256) k_final(const float* __restrict__ x,
                                               const float* __restrict__ bias,
                                               const float* __restrict__ alpha_p,
                                               float* __restrict__ out) {
    int t = threadIdx.x;
    int c0 = blockIdx.x * 1024 + t * 4;
    float a = alpha_p[0];
    float4 bb = *(const float4*)(bias + c0);
    float4 ab = make_float4(a * bb.x, a * bb.y, a * bb.z, a * bb.w);
    float scale = a * 0.25f;
    int vbase = blockIdx.y * 64;
    for (int vi = 0; vi < 64; vi++) {
        int v = vbase + vi;
        unsigned m = g_cmask[v];
        float4 xv = __ldcs((const float4*)(x + (size_t)v * CIN + c0));
        float4 o = make_float4(xv.x + ab.x, xv.y + ab.y, xv.z + ab.z, xv.w + ab.w);
        while (m) {
            int camid = __ffs(m) - 1;
            m &= m - 1;
            float4 cf = *(const float4*)(&g_coef[(v * NCAM + camid) * NH]);
            const float* hp = &g_hsrc[camid * NJ + c0];
            float u0 = scale * cf.x, u1 = scale * cf.y,
                  u2 = scale * cf.z, u3 = scale * cf.w;
            float4 h0 = *(const float4*)(hp);
            float4 h1 = *(const float4*)(hp + NCOUT);
            float4 h2 = *(const float4*)(hp + 2 * NCOUT);
            float4 h3 = *(const float4*)(hp + 3 * NCOUT);
            o.x += u0 * h0.x + u1 * h1.x + u2 * h2.x + u3 * h3.x;
            o.y += u0 * h0.y + u1 * h1.y + u2 * h2.y + u3 * h3.y;
            o.z += u0 * h0.z + u1 * h1.z + u2 * h2.z + u3 * h3.z;
            o.w += u0 * h0.w + u1 * h1.w + u2 * h2.w + u3 * h3.w;
        }
        *(float4*)(out + (size_t)v * CIN + c0) = o;
    }
}

// ---------------- launch ----------------
extern "C" void kernel_launch(void* const* d_in, const int* in_sizes, int n_in,
                              void* d_out, int out_size) {
    const float* x_vehicle = (const float*)d_in[0];
    const float* cam_table = (const float*)d_in[1];
    const float* W         = (const float*)d_in[2];
    const float* att_src   = (const float*)d_in[3];
    const float* att_dst   = (const float*)d_in[4];
    const float* bias      = (const float*)d_in[5];
    const float* alpha     = (const float*)d_in[6];
    // d_in[7] = unique_cams == arange(NCAM); identity gather skipped
    const void*  esrc      = d_in[8];
    const void*  edst      = d_in[9];
    float* out = (float*)d_out;

    k_zero<<<128, 256>>>(esrc);
    {
        dim3 g(32, KB);
        k_hsrc<<<g, 128>>>(W, cam_table, att_dst);
    }
    k_hred<<<(NCAM * NJ / 4) / 256, 256>>>(att_src);
    k_ad<<<NV / 16, 256>>>(x_vehicle);
    k_count<<<(NE + 127) / 128, 128>>>(esrc, edst);
    k_attn<<<NV / 256, 256>>>();
    {
        dim3 g(CIN / 1024, NV / 64);   // FIX: was NCOUT/1024*2 (OOB columns)
        k_final<<<g, 256>>>(x_vehicle, bias, alpha, out);
    }
}

// round 5
// speedup vs baseline: 1.1326x; 1.1326x over previous
#include <cuda_runtime.h>

#define NV    8192
#define NCAM  20
#define CIN   2048
#define NH    4
#define NCOUT 2048
#define NJ    8192      /* NH*NCOUT */
#define NE    16384
#define NEG_SLOPE 0.2f
#define KB    32        /* k-split chunks for h_src */
#define KC    64        /* K per chunk (KB*KC = CIN) */

typedef unsigned long long ull;

// ---------------- scratch (device globals; no allocation) ----------------
__device__ float    g_part[KB * NCAM * NJ];   // 21MB k-split partials
__device__ float    g_hsrc[NCAM * NJ];        // [cam][h*COUT + c]
__device__ float    g_wd[NH * CIN];           // [h][k]
__device__ float    g_as[NCAM * NH];
__device__ float    g_ad[NV * NH];
__device__ int      g_cnt[NV * NCAM];         // per-vehicle camera edge counts
__device__ unsigned g_cmask[NV];              // active-camera bitmask
__device__ float    g_coef[NV * NCAM * NH];   // softmax-weighted coefficients
__device__ int      g_is64;

// ---------------- helpers ----------------
__device__ __forceinline__ float warp_sum(float v) {
    #pragma unroll
    for (int o = 16; o; o >>= 1) v += __shfl_down_sync(0xffffffffu, v, o);
    return v;
}
__device__ __forceinline__ int eidx(const void* p, int i) {
    return g_is64 ? (int)((const long long*)p)[i] : ((const int*)p)[i];
}
// packed fp32x2 FMA: acc = w * c + acc  (both lanes)
#define FMA2(acc, w, c) \
    asm("fma.rn.f32x2 %0, %1, %2, %0;" : "+l"(acc) : "l"(w), "l"(c))

// ---------------- 1) zero accumulated scratch + int-width detect ----------------
__global__ void k_zero(const void* esrc) {
    int i = blockIdx.x * blockDim.x + threadIdx.x;
    if (i == 0) {
        const long long* p = (const long long*)esrc;
        int ok = 1;
        for (int q = 0; q < 64; q++) {
            long long v = p[q];
            if (v < 0 || v >= NCAM) { ok = 0; break; }
        }
        g_is64 = ok;
    }
    int s = gridDim.x * blockDim.x;
    for (int j = i; j < NV * NCAM; j += s) g_cnt[j] = 0;
    for (int j = i; j < NCAM * NH; j += s) g_as[j] = 0.f;
}

// ---------------- 2) wd[h][k] = sum_j W[k,j]*att_dst[j]  (64MB stream) ----------------
__global__ void __launch_bounds__(256) k_wd(const float* __restrict__ W,
                                            const float* __restrict__ att_dst) {
    int k = blockIdx.x, t = threadIdx.x;
    const float4* row = (const float4*)(W + (size_t)k * NJ);
    const float4* ad4 = (const float4*)att_dst;
    float part[NH] = {0.f, 0.f, 0.f, 0.f};
    #pragma unroll
    for (int i = 0; i < 8; i++) {
        int j4 = i * 256 + t;                 // head = i>>1
        float4 w = row[j4], a = ad4[j4];
        part[i >> 1] += w.x * a.x + w.y * a.y + w.z * a.z + w.w * a.w;
    }
    __shared__ float s[8][NH];
    int wid = t >> 5, lane = t & 31;
    #pragma unroll
    for (int h = 0; h < NH; h++) {
        float v = warp_sum(part[h]);
        if (lane == 0) s[wid][h] = v;
    }
    __syncthreads();
    if (t < NH) {
        float a = 0.f;
        #pragma unroll
        for (int w = 0; w < 8; w++) a += s[w][t];
        g_wd[t * CIN + k] = a;
    }
}

// ---------------- 3) edge counts ----------------
__global__ void k_count(const void* esrc, const void* edst) {
    int e = blockIdx.x * blockDim.x + threadIdx.x;
    if (e >= NE) return;
    int s = eidx(esrc, e), d = eidx(edst, e);
    atomicAdd(&g_cnt[d * NCAM + s], 1);
}

// ---------------- 4) h_src partials, packed f32x2 FMA ----------------
// grid (16 j-blocks of 512 cols, 32 k-chunks of 64); 128 threads; 4 cols/thread.
__global__ void __launch_bounds__(128) k_hsrc(const float* __restrict__ W,
                                              const float* __restrict__ cam) {
    int jb = blockIdx.x, kb = blockIdx.y, t = threadIdx.x;
    int k0 = kb * KC;
    int j0 = jb * 512 + t * 4;

    __shared__ ull s_cam2[NCAM][KC];        // camera scalar duplicated in both lanes
    for (int i = t; i < NCAM * KC; i += 128) {
        int n = i / KC, kc = i % KC;
        float c = cam[n * CIN + k0 + kc];
        float2 cc = make_float2(c, c);
        s_cam2[n][kc] = *(const ull*)&cc;
    }
    __syncthreads();

    ull acc[NCAM][2];
    #pragma unroll
    for (int n = 0; n < NCAM; n++) { acc[n][0] = 0ull; acc[n][1] = 0ull; }

    const float* Wp = W + (size_t)k0 * NJ + j0;
    #pragma unroll 2
    for (int kc = 0; kc < KC; kc++) {
        const ull* wp = (const ull*)(Wp + (size_t)kc * NJ);
        ull w0 = wp[0], w1 = wp[1];
        #pragma unroll
        for (int n = 0; n < NCAM; n++) {
            ull c2 = s_cam2[n][kc];
            FMA2(acc[n][0], w0, c2);
            FMA2(acc[n][1], w1, c2);
        }
    }

    float* pp = g_part + (size_t)kb * (NCAM * NJ) + j0;
    #pragma unroll
    for (int n = 0; n < NCAM; n++) {
        float2 lo = *(const float2*)&acc[n][0];
        float2 hi = *(const float2*)&acc[n][1];
        *(float4*)(pp + n * NJ) = make_float4(lo.x, lo.y, hi.x, hi.y);
    }
}

// ---------------- 5) reduce partials -> h_src (float4), fused a_s ----------------
__global__ void __launch_bounds__(256) k_hred(const float* __restrict__ att_src) {
    int gid = blockIdx.x * 256 + threadIdx.x;     // over NCAM*NJ/4 = 40960
    int lane = threadIdx.x & 31;
    int j4 = (gid % (NJ / 4));
    int cm = gid / (NJ / 4);
    int j = j4 * 4, h = j / NCOUT;
    float4 s = make_float4(0.f, 0.f, 0.f, 0.f);
    const float4* P = (const float4*)g_part;
    #pragma unroll 8
    for (int kb = 0; kb < KB; kb++) {
        float4 v = P[(size_t)kb * (NCAM * NJ / 4) + gid];
        s.x += v.x; s.y += v.y; s.z += v.z; s.w += v.w;
    }
    ((float4*)g_hsrc)[gid] = s;
    float4 a = *(const float4*)(att_src + j);
    float p = warp_sum(s.x * a.x + s.y * a.y + s.z * a.z + s.w * a.w);
    if (lane == 0) atomicAdd(&g_as[cm * NH + h], p);
}

// ---------------- 6) a_d: warp per vehicle, 16 per block (512 thr) ----------------
__global__ void __launch_bounds__(512) k_ad(const float* __restrict__ x) {
    __shared__ __align__(16) float s_wd[NH * CIN];   // 32KB
    int t = threadIdx.x, wid = t >> 5, lane = t & 31;
    for (int i = t; i < NH * CIN; i += 512) s_wd[i] = g_wd[i];
    __syncthreads();

    int v = blockIdx.x * 16 + wid;
    const float4* xr = (const float4*)(x + (size_t)v * CIN);
    const float4* wd4 = (const float4*)s_wd;
    float part[NH] = {0.f, 0.f, 0.f, 0.f};
    #pragma unroll 4
    for (int i = 0; i < 16; i++) {
        int idx = lane + i * 32;
        float4 a = xr[idx];
        #pragma unroll
        for (int h = 0; h < NH; h++) {
            float4 wq = wd4[h * (CIN / 4) + idx];
            part[h] += a.x * wq.x + a.y * wq.y + a.z * wq.z + a.w * wq.w;
        }
    }
    #pragma unroll
    for (int h = 0; h < NH; h++) {
        float s0 = warp_sum(part[h]);
        if (lane == 0) g_ad[v * NH + h] = s0;
    }
}

// ---------------- 7) per-vehicle softmax over active cameras ----------------
__global__ void k_attn() {
    int v = blockIdx.x * blockDim.x + threadIdx.x;
    if (v >= NV) return;
    unsigned mask = 0;
    int cnt[NCAM];
    const int4* cp = (const int4*)&g_cnt[v * NCAM];
    #pragma unroll
    for (int q = 0; q < 5; q++) {
        int4 c4 = cp[q];
        cnt[q * 4 + 0] = c4.x; cnt[q * 4 + 1] = c4.y;
        cnt[q * 4 + 2] = c4.z; cnt[q * 4 + 3] = c4.w;
    }
    #pragma unroll
    for (int s = 0; s < NCAM; s++) if (cnt[s]) mask |= 1u << s;
    g_cmask[v] = mask;
    if (!mask) return;
    float4 adv = *(const float4*)&g_ad[v * NH];
    float ad[NH] = {adv.x, adv.y, adv.z, adv.w};
    float m[NH] = {-1e30f, -1e30f, -1e30f, -1e30f};
    unsigned mm = mask;
    while (mm) {
        int s = __ffs(mm) - 1; mm &= mm - 1;
        #pragma unroll
        for (int h = 0; h < NH; h++) {
            float z = g_as[s * NH + h] + ad[h];
            z = (z > 0.f) ? z : NEG_SLOPE * z;
            m[h] = fmaxf(m[h], z);
        }
    }
    float den[NH] = {0.f, 0.f, 0.f, 0.f};
    mm = mask;
    while (mm) {
        int s = __ffs(mm) - 1; mm &= mm - 1;
        float p[NH];
        #pragma unroll
        for (int h = 0; h < NH; h++) {
            float z = g_as[s * NH + h] + ad[h];
            z = (z > 0.f) ? z : NEG_SLOPE * z;
            p[h] = (float)cnt[s] * expf(z - m[h]);
            den[h] += p[h];
        }
        *(float4*)&g_coef[(v * NCAM + s) * NH] = make_float4(p[0], p[1], p[2], p[3]);
    }
    float4 r = make_float4(1.f / den[0], 1.f / den[1], 1.f / den[2], 1.f / den[3]);
    mm = mask;
    while (mm) {
        int s = __ffs(mm) - 1; mm &= mm - 1;
        float4 pv = *(const float4*)&g_coef[(v * NCAM + s) * NH];
        pv.x *= r.x; pv.y *= r.y; pv.z *= r.z; pv.w *= r.w;
        *(float4*)&g_coef[(v * NCAM + s) * NH] = pv;
    }
}

// ---------------- 8) fused epilogue ----------------
// 512-col tiles (per-cam slice = 160KB, L1-resident); 4-vehicle unroll for MLP.
__global__ void __launch_bounds__(128) k_final(const float* __restrict__ x,
                                               const float* __restrict__ bias,
                                               const float* __restrict__ alpha_p,
                                               float* __restrict__ out) {
    int t = threadIdx.x;
    int c0 = blockIdx.x * 512 + t * 4;    // grid.x = 4
    float a = alpha_p[0];
    float4 bb = *(const float4*)(bias + c0);
    float4 ab = make_float4(a * bb.x, a * bb.y, a * bb.z, a * bb.w);
    float scale = a * 0.25f;
    int vbase = blockIdx.y * 64;          // grid.y = 128
    for (int vi = 0; vi < 64; vi += 4) {
        int v = vbase + vi;
        uint4 mv = *(const uint4*)&g_cmask[v];
        unsigned mk[4] = {mv.x, mv.y, mv.z, mv.w};
        float4 xv[4];
        #pragma unroll
        for (int p = 0; p < 4; p++)
            xv[p] = *(const float4*)(x + (size_t)(v + p) * CIN + c0);
        #pragma unroll
        for (int p = 0; p < 4; p++) {
            float4 o = make_float4(xv[p].x + ab.x, xv[p].y + ab.y,
                                   xv[p].z + ab.z, xv[p].w + ab.w);
            unsigned m = mk[p];
            while (m) {
                int camid = __ffs(m) - 1;
                m &= m - 1;
                float4 cf = *(const float4*)(&g_coef[((v + p) * NCAM + camid) * NH]);
                const float* hp = &g_hsrc[camid * NJ + c0];
                float u0 = scale * cf.x, u1 = scale * cf.y,
                      u2 = scale * cf.z, u3 = scale * cf.w;
                float4 h0 = *(const float4*)(hp);
                float4 h1 = *(const float4*)(hp + NCOUT);
                float4 h2 = *(const float4*)(hp + 2 * NCOUT);
                float4 h3 = *(const float4*)(hp + 3 * NCOUT);
                o.x += u0 * h0.x + u1 * h1.x + u2 * h2.x + u3 * h3.x;
                o.y += u0 * h0.y + u1 * h1.y + u2 * h2.y + u3 * h3.y;
                o.z += u0 * h0.z + u1 * h1.z + u2 * h2.z + u3 * h3.z;
                o.w += u0 * h0.w + u1 * h1.w + u2 * h2.w + u3 * h3.w;
            }
            __stcs((float4*)(out + (size_t)(v + p) * CIN + c0), o);
        }
    }
}

// ---------------- launch ----------------
extern "C" void kernel_launch(void* const* d_in, const int* in_sizes, int n_in,
                              void* d_out, int out_size) {
    const float* x_vehicle = (const float*)d_in[0];
    const float* cam_table = (const float*)d_in[1];
    const float* W         = (const float*)d_in[2];
    const float* att_src   = (const float*)d_in[3];
    const float* att_dst   = (const float*)d_in[4];
    const float* bias      = (const float*)d_in[5];
    const float* alpha     = (const float*)d_in[6];
    // d_in[7] = unique_cams == arange(NCAM); identity gather skipped
    const void*  esrc      = d_in[8];
    const void*  edst      = d_in[9];
    float* out = (float*)d_out;

    k_zero<<<128, 256>>>(esrc);                       // 1
    k_wd<<<CIN, 256>>>(W, att_dst);                   // 2
    k_count<<<(NE + 127) / 128, 128>>>(esrc, edst);   // 3
    {
        dim3 g(16, KB);
        k_hsrc<<<g, 128>>>(W, cam_table);             // 4  <- profiled launch
    }
    k_hred<<<(NCAM * NJ / 4) / 256, 256>>>(att_src);  // 5
    k_ad<<<NV / 16, 512>>>(x_vehicle);                // 6
    k_attn<<<NV / 256, 256>>>();                      // 7
    {
        dim3 g(4, NV / 64);
        k_final<<<g, 128>>>(x_vehicle, bias, alpha, out); // 8
    }
}

// round 6
// speedup vs baseline: 1.3035x; 1.1509x over previous
#include <cuda_runtime.h>

#define NV    8192
#define NCAM  20
#define CIN   2048
#define NH    4
#define NCOUT 2048
#define NJ    8192      /* NH*NCOUT */
#define NE    16384
#define NEG_SLOPE 0.2f
#define KB    32        /* k-split chunks for h_src */
#define KC    64        /* K per chunk (KB*KC = CIN) */

typedef unsigned long long ull;

// ---------------- scratch (device globals; no allocation) ----------------
__device__ float    g_part[KB * NCAM * NJ];   // 21MB k-split partials
__device__ float    g_hsrc[NCAM * NJ];        // [cam][h*COUT + c]
__device__ float    g_wd[NH * CIN];           // [h][k]
__device__ float    g_as[NCAM * NH];
__device__ float    g_ad[NV * NH];
__device__ int      g_cnt[NV * NCAM];         // per-vehicle camera edge counts
__device__ unsigned g_cmask[NV];              // active-camera bitmask
__device__ float    g_coef[NV * NCAM * NH];   // softmax-weighted coefficients
__device__ int      g_is64;

// ---------------- helpers ----------------
__device__ __forceinline__ float warp_sum(float v) {
    #pragma unroll
    for (int o = 16; o; o >>= 1) v += __shfl_down_sync(0xffffffffu, v, o);
    return v;
}
__device__ __forceinline__ int eidx(const void* p, int i) {
    return g_is64 ? (int)((const long long*)p)[i] : ((const int*)p)[i];
}
// packed fp32x2 FMA: acc = w * c + acc  (both lanes)
#define FMA2(acc, w, c) \
    asm("fma.rn.f32x2 %0, %1, %2, %0;" : "+l"(acc) : "l"(w), "l"(c))

// ---------------- 1) zero accumulated scratch + int-width detect ----------------
__global__ void k_zero(const void* esrc) {
    int i = blockIdx.x * blockDim.x + threadIdx.x;
    if (i == 0) {
        const long long* p = (const long long*)esrc;
        int ok = 1;
        for (int q = 0; q < 64; q++) {
            long long v = p[q];
            if (v < 0 || v >= NCAM) { ok = 0; break; }
        }
        g_is64 = ok;
    }
    int s = gridDim.x * blockDim.x;
    for (int j = i; j < NV * NCAM; j += s) g_cnt[j] = 0;
    for (int j = i; j < NCAM * NH; j += s) g_as[j] = 0.f;
}

// ================= MEGA-1: hsrc (blocks 0..255) | wd (256..2303) | count (2304..2367)
#define M1_HSRC 256
#define M1_WD   (M1_HSRC + CIN)
#define M1_CNT  (M1_WD + NE / 256)

__global__ void __launch_bounds__(256, 2) k_mega1(const float* __restrict__ W,
                                                  const float* __restrict__ cam,
                                                  const float* __restrict__ att_dst,
                                                  const void* esrc, const void* edst) {
    int b = blockIdx.x, t = threadIdx.x;

    if (b < M1_HSRC) {
        // ---- h_src partials: 8 j-blocks of 1024 cols x 32 k-chunks of 64 ----
        int jb = b & 7, kb = b >> 3;
        int k0 = kb * KC;
        int j0 = jb * 1024 + t * 4;

        // camera scalars duplicated: [n][kc/2] = {(c0,c0),(c1,c1)} (16B)
        __shared__ ulonglong2 s_cam2[NCAM][KC / 2];   // 10KB
        for (int i = t; i < NCAM * KC; i += 256) {
            int n = i / KC, kc = i % KC;
            float c = cam[n * CIN + k0 + kc];
            float2 cc = make_float2(c, c);
            ((ull*)s_cam2)[n * KC + kc] = *(const ull*)&cc;
        }
        __syncthreads();

        ull acc[NCAM][2];
        #pragma unroll
        for (int n = 0; n < NCAM; n++) { acc[n][0] = 0ull; acc[n][1] = 0ull; }

        const float* Wp = W + (size_t)k0 * NJ + j0;
        #pragma unroll 2
        for (int kc2 = 0; kc2 < KC / 2; kc2++) {
            longlong2 w0 = *(const longlong2*)(Wp + (size_t)(2 * kc2) * NJ);
            longlong2 w1 = *(const longlong2*)(Wp + (size_t)(2 * kc2 + 1) * NJ);
            #pragma unroll
            for (int n = 0; n < NCAM; n++) {
                ulonglong2 cc = s_cam2[n][kc2];     // one LDS.128 feeds 2 kc
                FMA2(acc[n][0], (ull)w0.x, cc.x);
                FMA2(acc[n][1], (ull)w0.y, cc.x);
                FMA2(acc[n][0], (ull)w1.x, cc.y);
                FMA2(acc[n][1], (ull)w1.y, cc.y);
            }
        }

        float* pp = g_part + (size_t)kb * (NCAM * NJ) + j0;
        #pragma unroll
        for (int n = 0; n < NCAM; n++) {
            float2 lo = *(const float2*)&acc[n][0];
            float2 hi = *(const float2*)&acc[n][1];
            *(float4*)(pp + n * NJ) = make_float4(lo.x, lo.y, hi.x, hi.y);
        }
    } else if (b < M1_WD) {
        // ---- wd[h][k] = sum_j W[k,j]*att_dst[j] (64MB stream, overlaps hsrc) ----
        int k = b - M1_HSRC;
        const float4* row = (const float4*)(W + (size_t)k * NJ);
        const float4* ad4 = (const float4*)att_dst;
        float part[NH] = {0.f, 0.f, 0.f, 0.f};
        #pragma unroll
        for (int i = 0; i < 8; i++) {
            int j4 = i * 256 + t;
            float4 w = row[j4], a = ad4[j4];
            part[i >> 1] += w.x * a.x + w.y * a.y + w.z * a.z + w.w * a.w;
        }
        __shared__ float s[8][NH];
        int wid = t >> 5, lane = t & 31;
        #pragma unroll
        for (int h = 0; h < NH; h++) {
            float v = warp_sum(part[h]);
            if (lane == 0) s[wid][h] = v;
        }
        __syncthreads();
        if (t < NH) {
            float a = 0.f;
            #pragma unroll
            for (int w = 0; w < 8; w++) a += s[w][t];
            g_wd[t * CIN + k] = a;
        }
    } else {
        // ---- edge counts ----
        int e = (b - M1_WD) * 256 + t;
        if (e < NE) {
            int s = eidx(esrc, e), d = eidx(edst, e);
            atomicAdd(&g_cnt[d * NCAM + s], 1);
        }
    }
}

// ================= MEGA-2: a_d (blocks 0..1023) | hred (1024..1183)
#define M2_AD 1024

__global__ void __launch_bounds__(256) k_mega2(const float* __restrict__ x,
                                               const float* __restrict__ att_src) {
    int b = blockIdx.x, t = threadIdx.x;
    if (b < M2_AD) {
        // ---- a_d: warp per vehicle, 8 per block ----
        __shared__ __align__(16) float s_wd[NH * CIN];   // 32KB
        int wid = t >> 5, lane = t & 31;
        for (int i = t; i < NH * CIN; i += 256) s_wd[i] = g_wd[i];
        __syncthreads();
        int v = b * 8 + wid;
        const float4* xr = (const float4*)(x + (size_t)v * CIN);
        const float4* wd4 = (const float4*)s_wd;
        float part[NH] = {0.f, 0.f, 0.f, 0.f};
        #pragma unroll 4
        for (int i = 0; i < 16; i++) {
            int idx = lane + i * 32;
            float4 a = xr[idx];
            #pragma unroll
            for (int h = 0; h < NH; h++) {
                float4 wq = wd4[h * (CIN / 4) + idx];
                part[h] += a.x * wq.x + a.y * wq.y + a.z * wq.z + a.w * wq.w;
            }
        }
        #pragma unroll
        for (int h = 0; h < NH; h++) {
            float s0 = warp_sum(part[h]);
            if (lane == 0) g_ad[v * NH + h] = s0;
        }
    } else {
        // ---- reduce partials -> h_src (float4), fused a_s ----
        int gid = (b - M2_AD) * 256 + t;      // over NCAM*NJ/4 = 40960
        int lane = t & 31;
        int j4 = gid % (NJ / 4);
        int cm = gid / (NJ / 4);
        int j = j4 * 4, h = j / NCOUT;
        float4 s = make_float4(0.f, 0.f, 0.f, 0.f);
        const float4* P = (const float4*)g_part;
        #pragma unroll 8
        for (int kb = 0; kb < KB; kb++) {
            float4 v = P[(size_t)kb * (NCAM * NJ / 4) + gid];
            s.x += v.x; s.y += v.y; s.z += v.z; s.w += v.w;
        }
        ((float4*)g_hsrc)[gid] = s;
        float4 a = *(const float4*)(att_src + j);
        float p = warp_sum(s.x * a.x + s.y * a.y + s.z * a.z + s.w * a.w);
        if (lane == 0) atomicAdd(&g_as[cm * NH + h], p);
    }
}

// ---------------- per-vehicle softmax over active cameras ----------------
__global__ void k_attn() {
    int v = blockIdx.x * blockDim.x + threadIdx.x;
    if (v >= NV) return;
    unsigned mask = 0;
    int cnt[NCAM];
    const int4* cp = (const int4*)&g_cnt[v * NCAM];
    #pragma unroll
    for (int q = 0; q < 5; q++) {
        int4 c4 = cp[q];
        cnt[q * 4 + 0] = c4.x; cnt[q * 4 + 1] = c4.y;
        cnt[q * 4 + 2] = c4.z; cnt[q * 4 + 3] = c4.w;
    }
    #pragma unroll
    for (int s = 0; s < NCAM; s++) if (cnt[s]) mask |= 1u << s;
    g_cmask[v] = mask;
    if (!mask) return;
    float4 adv = *(const float4*)&g_ad[v * NH];
    float ad[NH] = {adv.x, adv.y, adv.z, adv.w};
    float m[NH] = {-1e30f, -1e30f, -1e30f, -1e30f};
    unsigned mm = mask;
    while (mm) {
        int s = __ffs(mm) - 1; mm &= mm - 1;
        #pragma unroll
        for (int h = 0; h < NH; h++) {
            float z = g_as[s * NH + h] + ad[h];
            z = (z > 0.f) ? z : NEG_SLOPE * z;
            m[h] = fmaxf(m[h], z);
        }
    }
    float den[NH] = {0.f, 0.f, 0.f, 0.f};
    mm = mask;
    while (mm) {
        int s = __ffs(mm) - 1; mm &= mm - 1;
        float p[NH];
        #pragma unroll
        for (int h = 0; h < NH; h++) {
            float z = g_as[s * NH + h] + ad[h];
            z = (z > 0.f) ? z : NEG_SLOPE * z;
            p[h] = (float)cnt[s] * expf(z - m[h]);
            den[h] += p[h];
        }
        *(float4*)&g_coef[(v * NCAM + s) * NH] = make_float4(p[0], p[1], p[2], p[3]);
    }
    float4 r = make_float4(1.f / den[0], 1.f / den[1], 1.f / den[2], 1.f / den[3]);
    mm = mask;
    while (mm) {
        int s = __ffs(mm) - 1; mm &= mm - 1;
        float4 pv = *(const float4*)&g_coef[(v * NCAM + s) * NH];
        pv.x *= r.x; pv.y *= r.y; pv.z *= r.z; pv.w *= r.w;
        *(float4*)&g_coef[(v * NCAM + s) * NH] = pv;
    }
}

// ---------------- fused epilogue ----------------
// 512-col tiles (per-cam slice = 160KB, L1-resident); 4-vehicle unroll for MLP.
__global__ void __launch_bounds__(128) k_final(const float* __restrict__ x,
                                               const float* __restrict__ bias,
                                               const float* __restrict__ alpha_p,
                                               float* __restrict__ out) {
    int t = threadIdx.x;
    int c0 = blockIdx.x * 512 + t * 4;    // grid.x = 4
    float a = alpha_p[0];
    float4 bb = *(const float4*)(bias + c0);
    float4 ab = make_float4(a * bb.x, a * bb.y, a * bb.z, a * bb.w);
    float scale = a * 0.25f;
    int vbase = blockIdx.y * 64;          // grid.y = 128
    for (int vi = 0; vi < 64; vi += 4) {
        int v = vbase + vi;
        uint4 mv = *(const uint4*)&g_cmask[v];
        unsigned mk[4] = {mv.x, mv.y, mv.z, mv.w};
        float4 xv[4];
        #pragma unroll
        for (int p = 0; p < 4; p++)
            xv[p] = *(const float4*)(x + (size_t)(v + p) * CIN + c0);
        #pragma unroll
        for (int p = 0; p < 4; p++) {
            float4 o = make_float4(xv[p].x + ab.x, xv[p].y + ab.y,
                                   xv[p].z + ab.z, xv[p].w + ab.w);
            unsigned m = mk[p];
            while (m) {
                int camid = __ffs(m) - 1;
                m &= m - 1;
                float4 cf = *(const float4*)(&g_coef[((v + p) * NCAM + camid) * NH]);
                const float* hp = &g_hsrc[camid * NJ + c0];
                float u0 = scale * cf.x, u1 = scale * cf.y,
                      u2 = scale * cf.z, u3 = scale * cf.w;
                float4 h0 = *(const float4*)(hp);
                float4 h1 = *(const float4*)(hp + NCOUT);
                float4 h2 = *(const float4*)(hp + 2 * NCOUT);
                float4 h3 = *(const float4*)(hp + 3 * NCOUT);
                o.x += u0 * h0.x + u1 * h1.x + u2 * h2.x + u3 * h3.x;
                o.y += u0 * h0.y + u1 * h1.y + u2 * h2.y + u3 * h3.y;
                o.z += u0 * h0.z + u1 * h1.z + u2 * h2.z + u3 * h3.z;
                o.w += u0 * h0.w + u1 * h1.w + u2 * h2.w + u3 * h3.w;
            }
            __stcs((float4*)(out + (size_t)(v + p) * CIN + c0), o);
        }
    }
}

// ---------------- launch ----------------
extern "C" void kernel_launch(void* const* d_in, const int* in_sizes, int n_in,
                              void* d_out, int out_size) {
    const float* x_vehicle = (const float*)d_in[0];
    const float* cam_table = (const float*)d_in[1];
    const float* W         = (const float*)d_in[2];
    const float* att_src   = (const float*)d_in[3];
    const float* att_dst   = (const float*)d_in[4];
    const float* bias      = (const float*)d_in[5];
    const float* alpha     = (const float*)d_in[6];
    // d_in[7] = unique_cams == arange(NCAM); identity gather skipped
    const void*  esrc      = d_in[8];
    const void*  edst      = d_in[9];
    float* out = (float*)d_out;

    k_zero<<<128, 256>>>(esrc);                                     // 1
    k_mega1<<<M1_CNT, 256>>>(W, cam_table, att_dst, esrc, edst);    // 2
    k_mega2<<<M2_AD + (NCAM * NJ / 4) / 256, 256>>>(x_vehicle, att_src); // 3
    k_attn<<<NV / 256, 256>>>();                                    // 4
    {
        dim3 g(4, NV / 64);
        k_final<<<g, 128>>>(x_vehicle, bias, alpha, out);           // 5
    }
}

// round 7
// speedup vs baseline: 1.6489x; 1.2649x over previous
#include <cuda_runtime.h>

#define NV    8192
#define NCAM  20
#define CIN   2048
#define NH    4
#define NCOUT 2048
#define NJ    8192      /* NH*NCOUT */
#define NE    16384
#define NEG_SLOPE 0.2f
#define KB    32        /* k-split chunks for h_src */
#define KC    64        /* K per chunk (KB*KC = CIN) */

typedef unsigned long long ull;

// ---------------- scratch (device globals; no allocation) ----------------
__device__ float    g_part[KB * NCAM * NJ];   // 21MB k-split partials
__device__ float    g_hsrc[NCAM * NJ];        // [cam][h*COUT + c]
__device__ float    g_wd[NH * CIN];           // [h][k]
__device__ float    g_as[NCAM * NH];
__device__ float    g_ad[NV * NH];
__device__ int      g_cnt[NV * NCAM];         // per-vehicle camera edge counts
__device__ int      g_is64;

// ---------------- helpers ----------------
__device__ __forceinline__ float warp_sum(float v) {
    #pragma unroll
    for (int o = 16; o; o >>= 1) v += __shfl_down_sync(0xffffffffu, v, o);
    return v;
}
__device__ __forceinline__ int eidx(const void* p, int i) {
    return g_is64 ? (int)((const long long*)p)[i] : ((const int*)p)[i];
}
// packed fp32x2 FMA: acc = w * c + acc  (both lanes)
#define FMA2(acc, w, c) \
    asm("fma.rn.f32x2 %0, %1, %2, %0;" : "+l"(acc) : "l"(w), "l"(c))

// ---------------- 1) zero accumulated scratch + int-width detect ----------------
__global__ void k_zero(const void* esrc) {
    int i = blockIdx.x * blockDim.x + threadIdx.x;
    if (i == 0) {
        const long long* p = (const long long*)esrc;
        int ok = 1;
        for (int q = 0; q < 64; q++) {
            long long v = p[q];
            if (v < 0 || v >= NCAM) { ok = 0; break; }
        }
        g_is64 = ok;
    }
    int s = gridDim.x * blockDim.x;
    for (int j = i; j < NV * NCAM; j += s) g_cnt[j] = 0;
    for (int j = i; j < NCAM * NH; j += s) g_as[j] = 0.f;
}

// ================= MEGA-1: hsrc (blocks 0..255) | wd (256..2303) | count (2304..2367)
#define M1_HSRC 256
#define M1_WD   (M1_HSRC + CIN)
#define M1_CNT  (M1_WD + NE / 256)

__global__ void __launch_bounds__(256, 2) k_mega1(const float* __restrict__ W,
                                                  const float* __restrict__ cam,
                                                  const float* __restrict__ att_dst,
                                                  const void* esrc, const void* edst) {
    int b = blockIdx.x, t = threadIdx.x;

    if (b < M1_HSRC) {
        // ---- h_src partials: 8 j-blocks of 1024 cols x 32 k-chunks of 64 ----
        int jb = b & 7, kb = b >> 3;
        int k0 = kb * KC;
        int j0 = jb * 1024 + t * 4;

        // camera scalars duplicated: [n][kc/2] = {(c0,c0),(c1,c1)} (16B)
        __shared__ ulonglong2 s_cam2[NCAM][KC / 2];   // 10KB
        for (int i = t; i < NCAM * KC; i += 256) {
            int n = i / KC, kc = i % KC;
            float c = cam[n * CIN + k0 + kc];
            float2 cc = make_float2(c, c);
            ((ull*)s_cam2)[n * KC + kc] = *(const ull*)&cc;
        }
        __syncthreads();

        ull acc[NCAM][2];
        #pragma unroll
        for (int n = 0; n < NCAM; n++) { acc[n][0] = 0ull; acc[n][1] = 0ull; }

        const float* Wp = W + (size_t)k0 * NJ + j0;
        #pragma unroll 2
        for (int kc2 = 0; kc2 < KC / 2; kc2++) {
            longlong2 w0 = *(const longlong2*)(Wp + (size_t)(2 * kc2) * NJ);
            longlong2 w1 = *(const longlong2*)(Wp + (size_t)(2 * kc2 + 1) * NJ);
            #pragma unroll
            for (int n = 0; n < NCAM; n++) {
                ulonglong2 cc = s_cam2[n][kc2];     // one LDS.128 feeds 2 kc
                FMA2(acc[n][0], (ull)w0.x, cc.x);
                FMA2(acc[n][1], (ull)w0.y, cc.x);
                FMA2(acc[n][0], (ull)w1.x, cc.y);
                FMA2(acc[n][1], (ull)w1.y, cc.y);
            }
        }

        float* pp = g_part + (size_t)kb * (NCAM * NJ) + j0;
        #pragma unroll
        for (int n = 0; n < NCAM; n++) {
            float2 lo = *(const float2*)&acc[n][0];
            float2 hi = *(const float2*)&acc[n][1];
            *(float4*)(pp + n * NJ) = make_float4(lo.x, lo.y, hi.x, hi.y);
        }
    } else if (b < M1_WD) {
        // ---- wd[h][k] = sum_j W[k,j]*att_dst[j] (64MB stream, overlaps hsrc) ----
        int k = b - M1_HSRC;
        const float4* row = (const float4*)(W + (size_t)k * NJ);
        const float4* ad4 = (const float4*)att_dst;
        float part[NH] = {0.f, 0.f, 0.f, 0.f};
        #pragma unroll
        for (int i = 0; i < 8; i++) {
            int j4 = i * 256 + t;
            float4 w = row[j4], a = ad4[j4];
            part[i >> 1] += w.x * a.x + w.y * a.y + w.z * a.z + w.w * a.w;
        }
        __shared__ float s[8][NH];
        int wid = t >> 5, lane = t & 31;
        #pragma unroll
        for (int h = 0; h < NH; h++) {
            float v = warp_sum(part[h]);
            if (lane == 0) s[wid][h] = v;
        }
        __syncthreads();
        if (t < NH) {
            float a = 0.f;
            #pragma unroll
            for (int w = 0; w < 8; w++) a += s[w][t];
            g_wd[t * CIN + k] = a;
        }
    } else {
        // ---- edge counts ----
        int e = (b - M1_WD) * 256 + t;
        if (e < NE) {
            int s = eidx(esrc, e), d = eidx(edst, e);
            atomicAdd(&g_cnt[d * NCAM + s], 1);
        }
    }
}

// ================= MEGA-2: a_d (blocks 0..1023) | hred (1024..1183)
#define M2_AD 1024

__global__ void __launch_bounds__(256) k_mega2(const float* __restrict__ x,
                                               const float* __restrict__ att_src) {
    int b = blockIdx.x, t = threadIdx.x;
    if (b < M2_AD) {
        // ---- a_d: warp per vehicle, 8 per block ----
        __shared__ __align__(16) float s_wd[NH * CIN];   // 32KB
        int wid = t >> 5, lane = t & 31;
        for (int i = t; i < NH * CIN; i += 256) s_wd[i] = g_wd[i];
        __syncthreads();
        int v = b * 8 + wid;
        const float4* xr = (const float4*)(x + (size_t)v * CIN);
        const float4* wd4 = (const float4*)s_wd;
        float part[NH] = {0.f, 0.f, 0.f, 0.f};
        #pragma unroll 4
        for (int i = 0; i < 16; i++) {
            int idx = lane + i * 32;
            float4 a = xr[idx];
            #pragma unroll
            for (int h = 0; h < NH; h++) {
                float4 wq = wd4[h * (CIN / 4) + idx];
                part[h] += a.x * wq.x + a.y * wq.y + a.z * wq.z + a.w * wq.w;
            }
        }
        #pragma unroll
        for (int h = 0; h < NH; h++) {
            float s0 = warp_sum(part[h]);
            if (lane == 0) g_ad[v * NH + h] = s0;
        }
    } else {
        // ---- reduce partials -> h_src (float4), fused a_s ----
        int gid = (b - M2_AD) * 256 + t;      // over NCAM*NJ/4 = 40960
        int lane = t & 31;
        int j4 = gid % (NJ / 4);
        int cm = gid / (NJ / 4);
        int j = j4 * 4, h = j / NCOUT;
        float4 s = make_float4(0.f, 0.f, 0.f, 0.f);
        const float4* P = (const float4*)g_part;
        #pragma unroll 8
        for (int kb = 0; kb < KB; kb++) {
            float4 v = P[(size_t)kb * (NCAM * NJ / 4) + gid];
            s.x += v.x; s.y += v.y; s.z += v.z; s.w += v.w;
        }
        ((float4*)g_hsrc)[gid] = s;
        float4 a = *(const float4*)(att_src + j);
        float p = warp_sum(s.x * a.x + s.y * a.y + s.z * a.z + s.w * a.w);
        if (lane == 0) atomicAdd(&g_as[cm * NH + h], p);
    }
}

// ---------------- fused epilogue with in-block softmax ----------------
// Prologue: threads 0..63 compute their vehicle's softmax over active cameras
// into smem (pre-scaled by alpha/4). Main loop: 512-col tiles, L1-resident
// h_src slices, 4-vehicle unroll.
__global__ void __launch_bounds__(128) k_final(const float* __restrict__ x,
                                               const float* __restrict__ bias,
                                               const float* __restrict__ alpha_p,
                                               float* __restrict__ out) {
    __shared__ float4   s_coef[64][NCAM];   // 20KB, pre-scaled coefficients
    __shared__ unsigned s_mask[64];

    int t = threadIdx.x;
    int vbase = blockIdx.y * 64;          // grid.y = 128
    float a = alpha_p[0];
    float scale = a * 0.25f;

    // ---- prologue: per-vehicle softmax (threads 0..63) ----
    if (t < 64) {
        int v = vbase + t;
        unsigned mask = 0;
        int cnt[NCAM];
        const int4* cp = (const int4*)&g_cnt[v * NCAM];
        #pragma unroll
        for (int q = 0; q < 5; q++) {
            int4 c4 = cp[q];
            cnt[q * 4 + 0] = c4.x; cnt[q * 4 + 1] = c4.y;
            cnt[q * 4 + 2] = c4.z; cnt[q * 4 + 3] = c4.w;
        }
        #pragma unroll
        for (int s = 0; s < NCAM; s++) if (cnt[s]) mask |= 1u << s;
        s_mask[t] = mask;
        if (mask) {
            float4 adv = *(const float4*)&g_ad[v * NH];
            float ad[NH] = {adv.x, adv.y, adv.z, adv.w};
            float m[NH] = {-1e30f, -1e30f, -1e30f, -1e30f};
            unsigned mm = mask;
            while (mm) {
                int s = __ffs(mm) - 1; mm &= mm - 1;
                #pragma unroll
                for (int h = 0; h < NH; h++) {
                    float z = g_as[s * NH + h] + ad[h];
                    z = (z > 0.f) ? z : NEG_SLOPE * z;
                    m[h] = fmaxf(m[h], z);
                }
            }
            float den[NH] = {0.f, 0.f, 0.f, 0.f};
            mm = mask;
            while (mm) {
                int s = __ffs(mm) - 1; mm &= mm - 1;
                float p[NH];
                #pragma unroll
                for (int h = 0; h < NH; h++) {
                    float z = g_as[s * NH + h] + ad[h];
                    z = (z > 0.f) ? z : NEG_SLOPE * z;
                    p[h] = (float)cnt[s] * expf(z - m[h]);
                    den[h] += p[h];
                }
                s_coef[t][s] = make_float4(p[0], p[1], p[2], p[3]);
            }
            float4 r = make_float4(scale / den[0], scale / den[1],
                                   scale / den[2], scale / den[3]);
            mm = mask;
            while (mm) {
                int s = __ffs(mm) - 1; mm &= mm - 1;
                float4 pv = s_coef[t][s];
                pv.x *= r.x; pv.y *= r.y; pv.z *= r.z; pv.w *= r.w;
                s_coef[t][s] = pv;
            }
        }
    }
    __syncthreads();

    // ---- main loop ----
    int c0 = blockIdx.x * 512 + t * 4;    // grid.x = 4
    float4 bb = *(const float4*)(bias + c0);
    float4 ab = make_float4(a * bb.x, a * bb.y, a * bb.z, a * bb.w);
    for (int vi = 0; vi < 64; vi += 4) {
        int v = vbase + vi;
        float4 xv[4];
        #pragma unroll
        for (int p = 0; p < 4; p++)
            xv[p] = *(const float4*)(x + (size_t)(v + p) * CIN + c0);
        #pragma unroll
        for (int p = 0; p < 4; p++) {
            float4 o = make_float4(xv[p].x + ab.x, xv[p].y + ab.y,
                                   xv[p].z + ab.z, xv[p].w + ab.w);
            unsigned m = s_mask[vi + p];
            while (m) {
                int camid = __ffs(m) - 1;
                m &= m - 1;
                float4 u = s_coef[vi + p][camid];   // pre-scaled
                const float* hp = &g_hsrc[camid * NJ + c0];
                float4 h0 = *(const float4*)(hp);
                float4 h1 = *(const float4*)(hp + NCOUT);
                float4 h2 = *(const float4*)(hp + 2 * NCOUT);
                float4 h3 = *(const float4*)(hp + 3 * NCOUT);
                o.x += u.x * h0.x + u.y * h1.x + u.z * h2.x + u.w * h3.x;
                o.y += u.x * h0.y + u.y * h1.y + u.z * h2.y + u.w * h3.y;
                o.z += u.x * h0.z + u.y * h1.z + u.z * h2.z + u.w * h3.z;
                o.w += u.x * h0.w + u.y * h1.w + u.z * h2.w + u.w * h3.w;
            }
            __stcs((float4*)(out + (size_t)(v + p) * CIN + c0), o);
        }
    }
}

// ---------------- launch ----------------
extern "C" void kernel_launch(void* const* d_in, const int* in_sizes, int n_in,
                              void* d_out, int out_size) {
    const float* x_vehicle = (const float*)d_in[0];
    const float* cam_table = (const float*)d_in[1];
    const float* W         = (const float*)d_in[2];
    const float* att_src   = (const float*)d_in[3];
    const float* att_dst   = (const float*)d_in[4];
    const float* bias      = (const float*)d_in[5];
    const float* alpha     = (const float*)d_in[6];
    // d_in[7] = unique_cams == arange(NCAM); identity gather skipped
    const void*  esrc      = d_in[8];
    const void*  edst      = d_in[9];
    float* out = (float*)d_out;

    k_zero<<<128, 256>>>(esrc);                                     // 1
    k_mega1<<<M1_CNT, 256>>>(W, cam_table, att_dst, esrc, edst);    // 2
    k_mega2<<<M2_AD + (NCAM * NJ / 4) / 256, 256>>>(x_vehicle, att_src); // 3
    {
        dim3 g(4, NV / 64);
        k_final<<<g, 128>>>(x_vehicle, bias, alpha, out);           // 4
    }
}

// round 8
// speedup vs baseline: 1.9085x; 1.1575x over previous
#include <cuda_runtime.h>

#define NV    8192
#define NCAM  20
#define CIN   2048
#define NH    4
#define NCOUT 2048
#define NJ    8192      /* NH*NCOUT */
#define NE    16384
#define NEG_SLOPE 0.2f
#define KB    32        /* k-split chunks for h_src */
#define KC    64        /* K per chunk (KB*KC = CIN) */

typedef unsigned long long ull;

// ---------------- scratch (device globals; no allocation) ----------------
__device__ float    g_part[KB * NCAM * NJ];   // 21MB k-split partials
__device__ float    g_hsrc[NCAM * NJ];        // [cam][h*COUT + c]
__device__ float    g_wd[NH * CIN];           // [h][k]
__device__ float    g_as[NCAM * NH];
__device__ float    g_ad[NV * NH];
__device__ int      g_cnt[NV * NCAM];         // per-vehicle camera edge counts
__device__ int      g_is64;

// ---------------- helpers ----------------
__device__ __forceinline__ float warp_sum(float v) {
    #pragma unroll
    for (int o = 16; o; o >>= 1) v += __shfl_down_sync(0xffffffffu, v, o);
    return v;
}
__device__ __forceinline__ int eidx(const void* p, int i) {
    return g_is64 ? (int)((const long long*)p)[i] : ((const int*)p)[i];
}
// packed fp32x2 FMA: acc = w * c + acc  (both lanes)
#define FMA2(acc, w, c) \
    asm("fma.rn.f32x2 %0, %1, %2, %0;" : "+l"(acc) : "l"(w), "l"(c))

// ---------------- 1) zero accumulated scratch + int-width detect ----------------
__global__ void k_zero(const void* esrc) {
    int i = blockIdx.x * blockDim.x + threadIdx.x;
    if (i == 0) {
        const long long* p = (const long long*)esrc;
        int ok = 1;
        for (int q = 0; q < 64; q++) {
            long long v = p[q];
            if (v < 0 || v >= NCAM) { ok = 0; break; }
        }
        g_is64 = ok;
    }
    int s = gridDim.x * blockDim.x;
    for (int j = i; j < NV * NCAM; j += s) g_cnt[j] = 0;
    for (int j = i; j < NCAM * NH; j += s) g_as[j] = 0.f;
}

// ================= MEGA-1: hsrc (blocks 0..255) | wd (256..2303) | count (2304..2367)
#define M1_HSRC 256
#define M1_WD   (M1_HSRC + CIN)
#define M1_CNT  (M1_WD + NE / 256)

__global__ void __launch_bounds__(256, 2) k_mega1(const float* __restrict__ W,
                                                  const float* __restrict__ cam,
                                                  const float* __restrict__ att_dst,
                                                  const void* esrc, const void* edst) {
    int b = blockIdx.x, t = threadIdx.x;

    if (b < M1_HSRC) {
        // ---- h_src partials: 8 j-blocks of 1024 cols x 32 k-chunks of 64 ----
        int jb = b & 7, kb = b >> 3;
        int k0 = kb * KC;
        int j0 = jb * 1024 + t * 4;

        // camera scalars duplicated: [n][kc/2] = {(c0,c0),(c1,c1)} (16B)
        __shared__ ulonglong2 s_cam2[NCAM][KC / 2];   // 10KB
        for (int i = t; i < NCAM * KC; i += 256) {
            int n = i / KC, kc = i % KC;
            float c = cam[n * CIN + k0 + kc];
            float2 cc = make_float2(c, c);
            ((ull*)s_cam2)[n * KC + kc] = *(const ull*)&cc;
        }
        __syncthreads();

        ull acc[NCAM][2];
        #pragma unroll
        for (int n = 0; n < NCAM; n++) { acc[n][0] = 0ull; acc[n][1] = 0ull; }

        const float* Wp = W + (size_t)k0 * NJ + j0;
        #pragma unroll 2
        for (int kc2 = 0; kc2 < KC / 2; kc2++) {
            longlong2 w0 = *(const longlong2*)(Wp + (size_t)(2 * kc2) * NJ);
            longlong2 w1 = *(const longlong2*)(Wp + (size_t)(2 * kc2 + 1) * NJ);
            #pragma unroll
            for (int n = 0; n < NCAM; n++) {
                ulonglong2 cc = s_cam2[n][kc2];     // one LDS.128 feeds 2 kc
                FMA2(acc[n][0], (ull)w0.x, cc.x);
                FMA2(acc[n][1], (ull)w0.y, cc.x);
                FMA2(acc[n][0], (ull)w1.x, cc.y);
                FMA2(acc[n][1], (ull)w1.y, cc.y);
            }
        }

        float* pp = g_part + (size_t)kb * (NCAM * NJ) + j0;
        #pragma unroll
        for (int n = 0; n < NCAM; n++) {
            float2 lo = *(const float2*)&acc[n][0];
            float2 hi = *(const float2*)&acc[n][1];
            *(float4*)(pp + n * NJ) = make_float4(lo.x, lo.y, hi.x, hi.y);
        }
    } else if (b < M1_WD) {
        // ---- wd[h][k] = sum_j W[k,j]*att_dst[j] (64MB stream, overlaps hsrc) ----
        int k = b - M1_HSRC;
        const float4* row = (const float4*)(W + (size_t)k * NJ);
        const float4* ad4 = (const float4*)att_dst;
        float part[NH] = {0.f, 0.f, 0.f, 0.f};
        #pragma unroll
        for (int i = 0; i < 8; i++) {
            int j4 = i * 256 + t;
            float4 w = row[j4], a = ad4[j4];
            part[i >> 1] += w.x * a.x + w.y * a.y + w.z * a.z + w.w * a.w;
        }
        __shared__ float s[8][NH];
        int wid = t >> 5, lane = t & 31;
        #pragma unroll
        for (int h = 0; h < NH; h++) {
            float v = warp_sum(part[h]);
            if (lane == 0) s[wid][h] = v;
        }
        __syncthreads();
        if (t < NH) {
            float a = 0.f;
            #pragma unroll
            for (int w = 0; w < 8; w++) a += s[w][t];
            g_wd[t * CIN + k] = a;
        }
    } else {
        // ---- edge counts ----
        int e = (b - M1_WD) * 256 + t;
        if (e < NE) {
            int s = eidx(esrc, e), d = eidx(edst, e);
            atomicAdd(&g_cnt[d * NCAM + s], 1);
        }
    }
}

// ================= MEGA-2: a_d (blocks 0..1023) | hred (1024..1183)
#define M2_AD 1024

__global__ void __launch_bounds__(256) k_mega2(const float* __restrict__ x,
                                               const float* __restrict__ att_src) {
    int b = blockIdx.x, t = threadIdx.x;
    if (b < M2_AD) {
        // ---- a_d: warp per vehicle, 8 per block ----
        __shared__ __align__(16) float s_wd[NH * CIN];   // 32KB
        int wid = t >> 5, lane = t & 31;
        for (int i = t; i < NH * CIN; i += 256) s_wd[i] = g_wd[i];
        __syncthreads();
        int v = b * 8 + wid;
        const float4* xr = (const float4*)(x + (size_t)v * CIN);
        const float4* wd4 = (const float4*)s_wd;
        float part[NH] = {0.f, 0.f, 0.f, 0.f};
        #pragma unroll 4
        for (int i = 0; i < 16; i++) {
            int idx = lane + i * 32;
            float4 a = xr[idx];
            #pragma unroll
            for (int h = 0; h < NH; h++) {
                float4 wq = wd4[h * (CIN / 4) + idx];
                part[h] += a.x * wq.x + a.y * wq.y + a.z * wq.z + a.w * wq.w;
            }
        }
        #pragma unroll
        for (int h = 0; h < NH; h++) {
            float s0 = warp_sum(part[h]);
            if (lane == 0) g_ad[v * NH + h] = s0;
        }
    } else {
        // ---- reduce partials -> h_src (float4), fused a_s ----
        int gid = (b - M2_AD) * 256 + t;      // over NCAM*NJ/4 = 40960
        int lane = t & 31;
        int j4 = gid % (NJ / 4);
        int cm = gid / (NJ / 4);
        int j = j4 * 4, h = j / NCOUT;
        float4 s = make_float4(0.f, 0.f, 0.f, 0.f);
        const float4* P = (const float4*)g_part;
        #pragma unroll 8
        for (int kb = 0; kb < KB; kb++) {
            float4 v = P[(size_t)kb * (NCAM * NJ / 4) + gid];
            s.x += v.x; s.y += v.y; s.z += v.z; s.w += v.w;
        }
        ((float4*)g_hsrc)[gid] = s;
        float4 a = *(const float4*)(att_src + j);
        float p = warp_sum(s.x * a.x + s.y * a.y + s.z * a.z + s.w * a.w);
        if (lane == 0) atomicAdd(&g_as[cm * NH + h], p);
    }
}

// ---------------- fused epilogue with in-block softmax ----------------
// 32 vehicles/block (grid 4x256 = 1024 blocks -> ~27 warps/SM) for latency
// hiding; 512-col tiles keep per-cam h_src slices L1/L2 resident.
__global__ void __launch_bounds__(128) k_final(const float* __restrict__ x,
                                               const float* __restrict__ bias,
                                               const float* __restrict__ alpha_p,
                                               float* __restrict__ out) {
    __shared__ float4   s_coef[32][NCAM];   // 10KB, pre-scaled coefficients
    __shared__ unsigned s_mask[32];

    int t = threadIdx.x;
    int vbase = blockIdx.y * 32;          // grid.y = 256
    float a = alpha_p[0];
    float scale = a * 0.25f;

    // ---- prologue: per-vehicle softmax (threads 0..31) ----
    if (t < 32) {
        int v = vbase + t;
        unsigned mask = 0;
        int cnt[NCAM];
        const int4* cp = (const int4*)&g_cnt[v * NCAM];
        #pragma unroll
        for (int q = 0; q < 5; q++) {
            int4 c4 = cp[q];
            cnt[q * 4 + 0] = c4.x; cnt[q * 4 + 1] = c4.y;
            cnt[q * 4 + 2] = c4.z; cnt[q * 4 + 3] = c4.w;
        }
        #pragma unroll
        for (int s = 0; s < NCAM; s++) if (cnt[s]) mask |= 1u << s;
        s_mask[t] = mask;
        if (mask) {
            float4 adv = *(const float4*)&g_ad[v * NH];
            float ad[NH] = {adv.x, adv.y, adv.z, adv.w};
            float m[NH] = {-1e30f, -1e30f, -1e30f, -1e30f};
            unsigned mm = mask;
            while (mm) {
                int s = __ffs(mm) - 1; mm &= mm - 1;
                #pragma unroll
                for (int h = 0; h < NH; h++) {
                    float z = g_as[s * NH + h] + ad[h];
                    z = (z > 0.f) ? z : NEG_SLOPE * z;
                    m[h] = fmaxf(m[h], z);
                }
            }
            float den[NH] = {0.f, 0.f, 0.f, 0.f};
            mm = mask;
            while (mm) {
                int s = __ffs(mm) - 1; mm &= mm - 1;
                float p[NH];
                #pragma unroll
                for (int h = 0; h < NH; h++) {
                    float z = g_as[s * NH + h] + ad[h];
                    z = (z > 0.f) ? z : NEG_SLOPE * z;
                    p[h] = (float)cnt[s] * expf(z - m[h]);
                    den[h] += p[h];
                }
                s_coef[t][s] = make_float4(p[0], p[1], p[2], p[3]);
            }
            float4 r = make_float4(scale / den[0], scale / den[1],
                                   scale / den[2], scale / den[3]);
            mm = mask;
            while (mm) {
                int s = __ffs(mm) - 1; mm &= mm - 1;
                float4 pv = s_coef[t][s];
                pv.x *= r.x; pv.y *= r.y; pv.z *= r.z; pv.w *= r.w;
                s_coef[t][s] = pv;
            }
        }
    }
    __syncthreads();

    // ---- main loop ----
    int c0 = blockIdx.x * 512 + t * 4;    // grid.x = 4
    float4 bb = *(const float4*)(bias + c0);
    float4 ab = make_float4(a * bb.x, a * bb.y, a * bb.z, a * bb.w);
    for (int vi = 0; vi < 32; vi += 4) {
        int v = vbase + vi;
        float4 xv[4];
        #pragma unroll
        for (int p = 0; p < 4; p++)
            xv[p] = *(const float4*)(x + (size_t)(v + p) * CIN + c0);
        #pragma unroll
        for (int p = 0; p < 4; p++) {
            float4 o = make_float4(xv[p].x + ab.x, xv[p].y + ab.y,
                                   xv[p].z + ab.z, xv[p].w + ab.w);
            unsigned m = s_mask[vi + p];
            while (m) {
                int camid = __ffs(m) - 1;
                m &= m - 1;
                float4 u = s_coef[vi + p][camid];   // pre-scaled
                const float* hp = &g_hsrc[camid * NJ + c0];
                float4 h0 = *(const float4*)(hp);
                float4 h1 = *(const float4*)(hp + NCOUT);
                float4 h2 = *(const float4*)(hp + 2 * NCOUT);
                float4 h3 = *(const float4*)(hp + 3 * NCOUT);
                o.x += u.x * h0.x + u.y * h1.x + u.z * h2.x + u.w * h3.x;
                o.y += u.x * h0.y + u.y * h1.y + u.z * h2.y + u.w * h3.y;
                o.z += u.x * h0.z + u.y * h1.z + u.z * h2.z + u.w * h3.z;
                o.w += u.x * h0.w + u.y * h1.w + u.z * h2.w + u.w * h3.w;
            }
            __stcs((float4*)(out + (size_t)(v + p) * CIN + c0), o);
        }
    }
}

// ---------------- launch ----------------
extern "C" void kernel_launch(void* const* d_in, const int* in_sizes, int n_in,
                              void* d_out, int out_size) {
    const float* x_vehicle = (const float*)d_in[0];
    const float* cam_table = (const float*)d_in[1];
    const float* W         = (const float*)d_in[2];
    const float* att_src   = (const float*)d_in[3];
    const float* att_dst   = (const float*)d_in[4];
    const float* bias      = (const float*)d_in[5];
    const float* alpha     = (const float*)d_in[6];
    // d_in[7] = unique_cams == arange(NCAM); identity gather skipped
    const void*  esrc      = d_in[8];
    const void*  edst      = d_in[9];
    float* out = (float*)d_out;

    k_zero<<<128, 256>>>(esrc);                                     // 1
    k_mega1<<<M1_CNT, 256>>>(W, cam_table, att_dst, esrc, edst);    // 2
    k_mega2<<<M2_AD + (NCAM * NJ / 4) / 256, 256>>>(x_vehicle, att_src); // 3
    {
        dim3 g(4, NV / 32);
        k_final<<<g, 128>>>(x_vehicle, bias, alpha, out);           // 4
    }
}